// round 12
// baseline (speedup 1.0000x reference)
#include <cuda_runtime.h>
#include <cstdint>

#define S_LEN 4096
#define D_DIM 1024
#define BATCH 4
#define TOK   (BATCH * S_LEN)   // 16384

__device__ float g_qkv[(size_t)3 * TOK * D_DIM];

__device__ __forceinline__ float rna_tf32(float x) {
    uint32_t u;
    asm("cvt.rna.tf32.f32 %0, %1;" : "=r"(u) : "f"(x));
    return __uint_as_float(u);
}

__device__ __forceinline__ void mma_tf32(float* d,
                                         uint32_t a0, uint32_t a1, uint32_t a2, uint32_t a3,
                                         uint32_t b0, uint32_t b1) {
    asm volatile(
        "mma.sync.aligned.m16n8k8.row.col.f32.tf32.tf32.f32 "
        "{%0,%1,%2,%3}, {%4,%5,%6,%7}, {%8,%9}, {%0,%1,%2,%3};"
        : "+f"(d[0]), "+f"(d[1]), "+f"(d[2]), "+f"(d[3])
        : "r"(a0), "r"(a1), "r"(a2), "r"(a3), "r"(b0), "r"(b1));
}

// ---------------------------------------------------------------------------
// Projection GEMM (tf32 mma) — unchanged (proven, ~720us)
// ---------------------------------------------------------------------------
#define XS_PITCH 20
#define WS_PITCH 136

__global__ __launch_bounds__(256, 2)
void proj_kernel(const float* __restrict__ X,
                 const float* __restrict__ Wq, const float* __restrict__ bq,
                 const float* __restrict__ Wk, const float* __restrict__ bk,
                 const float* __restrict__ Wv, const float* __restrict__ bv)
{
    const int z = blockIdx.z;
    const float* W    = (z == 0) ? Wq : (z == 1) ? Wk : Wv;
    const float* bias = (z == 0) ? bq : (z == 1) ? bk : bv;
    float* out = g_qkv + (size_t)z * TOK * D_DIM;

    const int m0 = blockIdx.y * 128;
    const int n0 = blockIdx.x * 128;

    __shared__ float Xs[2][128 * XS_PITCH];
    __shared__ float Ws[2][16 * WS_PITCH];

    const int t = threadIdx.x, w = t >> 5, lane = t & 31;
    const int wm = w >> 1, wn = w & 1;
    const int l4 = lane >> 2, lm = lane & 3;

    float acc[16][4];
#pragma unroll
    for (int i = 0; i < 16; ++i)
#pragma unroll
        for (int j = 0; j < 4; ++j) acc[i][j] = 0.f;

    float4 xa[2], wa[2];
#pragma unroll
    for (int i = 0; i < 2; ++i) {
        const int idx = t + i * 256;
        const int xr = idx >> 2, xq = idx & 3;
        xa[i] = *(const float4*)(X + (size_t)(m0 + xr) * D_DIM + xq * 4);
        const int wk = idx >> 5, nq = idx & 31;
        wa[i] = *(const float4*)(W + (size_t)wk * D_DIM + n0 + nq * 4);
    }
#pragma unroll
    for (int i = 0; i < 2; ++i) {
        const int idx = t + i * 256;
        const int xr = idx >> 2, xq = idx & 3;
        float* d = &Xs[0][xr * XS_PITCH + xq * 4];
        d[0] = rna_tf32(xa[i].x); d[1] = rna_tf32(xa[i].y);
        d[2] = rna_tf32(xa[i].z); d[3] = rna_tf32(xa[i].w);
        const int wk = idx >> 5, nq = idx & 31;
        float* d2 = &Ws[0][wk * WS_PITCH + nq * 4];
        d2[0] = rna_tf32(wa[i].x); d2[1] = rna_tf32(wa[i].y);
        d2[2] = rna_tf32(wa[i].z); d2[3] = rna_tf32(wa[i].w);
    }
    __syncthreads();

    for (int kt = 0; kt < 64; ++kt) {
        const int bf = kt & 1;
        if (kt < 63) {
#pragma unroll
            for (int i = 0; i < 2; ++i) {
                const int idx = t + i * 256;
                const int xr = idx >> 2, xq = idx & 3;
                xa[i] = *(const float4*)(X + (size_t)(m0 + xr) * D_DIM + (kt + 1) * 16 + xq * 4);
                const int wk = idx >> 5, nq = idx & 31;
                wa[i] = *(const float4*)(W + (size_t)((kt + 1) * 16 + wk) * D_DIM + n0 + nq * 4);
            }
        }
#pragma unroll
        for (int ks = 0; ks < 2; ++ks) {
            uint32_t a[2][4];
#pragma unroll
            for (int mt = 0; mt < 2; ++mt) {
                const float* Ar = &Xs[bf][(wm * 32 + mt * 16 + l4) * XS_PITCH + ks * 8 + lm];
                a[mt][0] = __float_as_uint(Ar[0]);
                a[mt][1] = __float_as_uint(Ar[8 * XS_PITCH]);
                a[mt][2] = __float_as_uint(Ar[4]);
                a[mt][3] = __float_as_uint(Ar[8 * XS_PITCH + 4]);
            }
            const float* Br = &Ws[bf][(ks * 8 + lm) * WS_PITCH + wn * 64 + l4];
#pragma unroll
            for (int nt = 0; nt < 8; ++nt) {
                const uint32_t b0 = __float_as_uint(Br[nt * 8]);
                const uint32_t b1 = __float_as_uint(Br[nt * 8 + 4 * WS_PITCH]);
                mma_tf32(acc[nt],     a[0][0], a[0][1], a[0][2], a[0][3], b0, b1);
                mma_tf32(acc[8 + nt], a[1][0], a[1][1], a[1][2], a[1][3], b0, b1);
            }
        }
        if (kt < 63) {
            const int nb = bf ^ 1;
#pragma unroll
            for (int i = 0; i < 2; ++i) {
                const int idx = t + i * 256;
                const int xr = idx >> 2, xq = idx & 3;
                float* d = &Xs[nb][xr * XS_PITCH + xq * 4];
                d[0] = rna_tf32(xa[i].x); d[1] = rna_tf32(xa[i].y);
                d[2] = rna_tf32(xa[i].z); d[3] = rna_tf32(xa[i].w);
                const int wk = idx >> 5, nq = idx & 31;
                float* d2 = &Ws[nb][wk * WS_PITCH + nq * 4];
                d2[0] = rna_tf32(wa[i].x); d2[1] = rna_tf32(wa[i].y);
                d2[2] = rna_tf32(wa[i].z); d2[3] = rna_tf32(wa[i].w);
            }
            __syncthreads();
        }
    }

#pragma unroll
    for (int mt = 0; mt < 2; ++mt) {
        const int r0 = m0 + wm * 32 + mt * 16 + l4;
#pragma unroll
        for (int nt = 0; nt < 8; ++nt) {
            const int cc = n0 + wn * 64 + nt * 8 + 2 * lm;
            const float bx = bias[cc], by = bias[cc + 1];
            float* a = acc[mt * 8 + nt];
            *(float2*)&out[(size_t)r0 * D_DIM + cc] =
                make_float2(rna_tf32(a[0] + bx), rna_tf32(a[1] + by));
            *(float2*)&out[(size_t)(r0 + 8) * D_DIM + cc] =
                make_float2(rna_tf32(a[2] + bx), rna_tf32(a[3] + by));
        }
    }
}

// ---------------------------------------------------------------------------
// Flash attention v4 = R2 skeleton (256 thr, 8 warps) + three deltas:
//  (1) key-permuted P/V mma mapping  -> V smem loads conflict-free
//  (2) no-rescale softmax            -> no per-chunk reductions/rescales
//  (3) single-barrier pipeline stage -> 16 barriers/chunk instead of ~35
// M=32 q/CTA, 64-key chunks, d staged 128/stage.
// S warp tile m16(wm) x n16(wn); PV warp tile m16(wm) x n32(wn).
// O = 128 floats/thread.
// ---------------------------------------------------------------------------
#define QSP 1028
#define KVP 140
#define PSP 68
#define KVB_F (64 * KVP)
#define ATTN_SM_FLOATS (32 * QSP + 2 * KVB_F + 32 * PSP + 128 + 32)

__global__ __launch_bounds__(256, 1)
void attn_kernel(float* __restrict__ out)
{
    extern __shared__ float sm[];
    float* Qs   = sm;                      // [32][1028]
    float* KVs  = Qs + 32 * QSP;           // [2][64][140]
    float* Ps   = KVs + 2 * KVB_F;         // [32][68], key-permuted columns
    float* redl = Ps + 32 * PSP;           // [32][4]
    float* l_s  = redl + 128;              // [32]

    const int t = threadIdx.x, w = t >> 5, lane = t & 31;
    const int wm = w >> 2, wn = w & 3;
    const int l4 = lane >> 2, lm = lane & 3;
    const int b = blockIdx.y;
    const int qtile = (int)gridDim.x - 1 - (int)blockIdx.x;   // heavy tiles first
    const int qbase = qtile * 32;

    const float* qg = g_qkv + (size_t)b * S_LEN * D_DIM + (size_t)qbase * D_DIM;
    const float* kg = g_qkv + (size_t)TOK * D_DIM     + (size_t)b * S_LEN * D_DIM;
    const float* vg = g_qkv + (size_t)2 * TOK * D_DIM + (size_t)b * S_LEN * D_DIM;

    const uint32_t kv_smem = (uint32_t)__cvta_generic_to_shared(KVs);

    // stage: 64 rows x 128 floats (2048 float4), 8 per thread, one commit group
    auto issue = [&](const float* base, int j0, int dc, int bfi) {
        const uint32_t dst = kv_smem + (uint32_t)bfi * (KVB_F * 4);
        const float* src0 = base + (size_t)j0 * D_DIM + dc * 128;
#pragma unroll
        for (int i = 0; i < 8; ++i) {
            const int idx = t + i * 256;
            const int row = idx >> 5, q4 = idx & 31;
            asm volatile("cp.async.cg.shared.global [%0], [%1], 16;"
                         :: "r"(dst + (uint32_t)(row * KVP + q4 * 4) * 4),
                            "l"(src0 + (size_t)row * D_DIM + q4 * 4)
                         : "memory");
        }
        asm volatile("cp.async.commit_group;" ::: "memory");
    };

    issue(kg, 0, 0, 0);   // prefetch K chunk0 stage0; overlaps Q staging

    // stage Q tile (already tf32-rounded by proj)
#pragma unroll
    for (int i = 0; i < 32; ++i) {
        const int idx = t + i * 256;
        const int row = idx >> 8, c4 = idx & 255;
        *(float4*)&Qs[row * QSP + c4 * 4] =
            *(const float4*)(qg + (size_t)row * D_DIM + c4 * 4);
    }

    float oacc[128];
#pragma unroll
    for (int i = 0; i < 128; ++i) oacc[i] = 0.f;
    float lsum0 = 0.f, lsum1 = 0.f;

    const int kcmax = (qbase + 31) >> 6;
    int bf = 0;

    for (int kc = 0; kc <= kcmax; ++kc) {
        const int j0 = kc << 6;
        float sacc[2][4] = {{0.f, 0.f, 0.f, 0.f}, {0.f, 0.f, 0.f, 0.f}};

        // ---- S = Q K^T, 8 stages of d=128, single barrier per stage ----
        for (int dc = 0; dc < 8; ++dc) {
            asm volatile("cp.async.wait_group 0;" ::: "memory");  // stage dc landed
            __syncthreads();                                      // all consumed bf^1
            if (dc < 7) issue(kg, j0, dc + 1, bf ^ 1);
            else        issue(vg, j0, 0,      bf ^ 1);

            const float* KB  = KVs + bf * KVB_F;
            const float* Qr0 = Qs + (wm * 16 + l4) * QSP + dc * 128;
            const float* Qr1 = Qr0 + 8 * QSP;
            const float* K0  = KB + (wn * 16 + l4) * KVP;
            const float* K1  = K0 + 8 * KVP;
#pragma unroll 4
            for (int ks = 0; ks < 16; ++ks) {
                const int c0 = ks * 8 + lm;
                const uint32_t a0 = __float_as_uint(Qr0[c0]);
                const uint32_t a1 = __float_as_uint(Qr1[c0]);
                const uint32_t a2 = __float_as_uint(Qr0[c0 + 4]);
                const uint32_t a3 = __float_as_uint(Qr1[c0 + 4]);
                const uint32_t b00 = __float_as_uint(K0[c0]);
                const uint32_t b01 = __float_as_uint(K0[c0 + 4]);
                const uint32_t b10 = __float_as_uint(K1[c0]);
                const uint32_t b11 = __float_as_uint(K1[c0 + 4]);
                mma_tf32(sacc[0], a0, a1, a2, a3, b00, b01);
                mma_tf32(sacc[1], a0, a1, a2, a3, b10, b11);
            }
            bf ^= 1;
        }

        // ---- softmax, no max-shift: p = exp(s/32); permuted P store ----
        // key (g*8 + 2j)   -> P col g*8 + j      (j = lm here)
        // key (g*8 + 2j+1) -> P col g*8 + 4 + j
        {
            const int row0 = qbase + wm * 16 + l4;
            float* Pr0 = Ps + (wm * 16 + l4) * PSP;
            float* Pr1 = Pr0 + 8 * PSP;
#pragma unroll
            for (int t8 = 0; t8 < 2; ++t8) {
                const int cb = j0 + wn * 16 + t8 * 8 + 2 * lm;
                const float p0 = (cb     <= row0)     ? __expf(sacc[t8][0] * 0.03125f) : 0.f;
                const float p1 = (cb + 1 <= row0)     ? __expf(sacc[t8][1] * 0.03125f) : 0.f;
                const float p2 = (cb     <= row0 + 8) ? __expf(sacc[t8][2] * 0.03125f) : 0.f;
                const float p3 = (cb + 1 <= row0 + 8) ? __expf(sacc[t8][3] * 0.03125f) : 0.f;
                lsum0 += p0 + p1;
                lsum1 += p2 + p3;
                const int cp = (wn * 2 + t8) * 8 + lm;
                Pr0[cp]     = rna_tf32(p0);
                Pr0[cp + 4] = rna_tf32(p1);
                Pr1[cp]     = rna_tf32(p2);
                Pr1[cp + 4] = rna_tf32(p3);
            }
        }
        // Ps stores are published by the first PV-stage barrier below.

        // ---- O += P @ V, 8 stages of d=128, key-permuted k-mapping ----
        for (int dc = 0; dc < 8; ++dc) {
            asm volatile("cp.async.wait_group 0;" ::: "memory");
            __syncthreads();
            if (dc < 7)          issue(vg, j0, dc + 1, bf ^ 1);
            else if (kc < kcmax) issue(kg, j0 + 64, 0, bf ^ 1);

            const float* VB  = KVs + bf * KVB_F;
            const float* Pr0 = Ps + (wm * 16 + l4) * PSP;
            const float* Pr1 = Pr0 + 8 * PSP;
#pragma unroll 2
            for (int ks = 0; ks < 8; ++ks) {
                const int cp = ks * 8 + lm;
                const uint32_t a0 = __float_as_uint(Pr0[cp]);       // key ks*8+2lm
                const uint32_t a1 = __float_as_uint(Pr1[cp]);
                const uint32_t a2 = __float_as_uint(Pr0[cp + 4]);   // key ks*8+2lm+1
                const uint32_t a3 = __float_as_uint(Pr1[cp + 4]);
                const float* Ve = VB + (ks * 8 + 2 * lm) * KVP + wn * 32 + l4;  // even key
                const float* Vo = Ve + KVP;                                     // odd key
#pragma unroll
                for (int nt = 0; nt < 4; ++nt) {
                    const uint32_t b0 = __float_as_uint(Ve[nt * 8]);
                    const uint32_t b1 = __float_as_uint(Vo[nt * 8]);
                    mma_tf32(&oacc[dc * 16 + nt * 4], a0, a1, a2, a3, b0, b1);
                }
            }
            bf ^= 1;
        }
    }

    // ---- final l reduction (once per kernel) ----
    lsum0 += __shfl_xor_sync(0xffffffffu, lsum0, 1);
    lsum0 += __shfl_xor_sync(0xffffffffu, lsum0, 2);
    lsum1 += __shfl_xor_sync(0xffffffffu, lsum1, 1);
    lsum1 += __shfl_xor_sync(0xffffffffu, lsum1, 2);
    if (lm == 0) {
        redl[(wm * 16 + l4) * 4 + wn]     = lsum0;
        redl[(wm * 16 + l4 + 8) * 4 + wn] = lsum1;
    }
    __syncthreads();
    if (t < 32)
        l_s[t] = redl[t * 4] + redl[t * 4 + 1] + redl[t * 4 + 2] + redl[t * 4 + 3];
    __syncthreads();

    const float inv0 = 1.0f / l_s[wm * 16 + l4];
    const float inv1 = 1.0f / l_s[wm * 16 + l4 + 8];
    float* og0 = out + (size_t)b * S_LEN * D_DIM + (size_t)(qbase + wm * 16 + l4) * D_DIM;
    float* og1 = og0 + 8 * D_DIM;
#pragma unroll
    for (int dc = 0; dc < 8; ++dc)
#pragma unroll
        for (int nt = 0; nt < 4; ++nt) {
            const int cc = dc * 128 + wn * 32 + nt * 8 + 2 * lm;
            const float* oa = &oacc[dc * 16 + nt * 4];
            *(float2*)&og0[cc] = make_float2(oa[0] * inv0, oa[1] * inv0);
            *(float2*)&og1[cc] = make_float2(oa[2] * inv1, oa[3] * inv1);
        }
}

// ---------------------------------------------------------------------------
extern "C" void kernel_launch(void* const* d_in, const int* in_sizes, int n_in,
                              void* d_out, int out_size)
{
    const float* x  = (const float*)d_in[0];
    const float* Wq = (const float*)d_in[1];
    const float* bq = (const float*)d_in[2];
    const float* Wk = (const float*)d_in[3];
    const float* bk = (const float*)d_in[4];
    const float* Wv = (const float*)d_in[5];
    const float* bv = (const float*)d_in[6];
    float* out = (float*)d_out;

    dim3 pg(D_DIM / 128, TOK / 128, 3);
    proj_kernel<<<pg, 256>>>(x, Wq, bq, Wk, bk, Wv, bv);

    const size_t attn_smem = (size_t)ATTN_SM_FLOATS * sizeof(float);   // ~212.6 KB
    cudaFuncSetAttribute(attn_kernel, cudaFuncAttributeMaxDynamicSharedMemorySize,
                         (int)attn_smem);
    dim3 ag(S_LEN / 32, BATCH);
    attn_kernel<<<ag, 256, attn_smem>>>(out);
}

// round 13
// speedup vs baseline: 1.0131x; 1.0131x over previous
#include <cuda_runtime.h>
#include <cstdint>

#define S_LEN 4096
#define D_DIM 1024
#define BATCH 4
#define TOK   (BATCH * S_LEN)   // 16384

__device__ float g_qkv[(size_t)3 * TOK * D_DIM];

__device__ __forceinline__ float rna_tf32(float x) {
    uint32_t u;
    asm("cvt.rna.tf32.f32 %0, %1;" : "=r"(u) : "f"(x));
    return __uint_as_float(u);
}

__device__ __forceinline__ void mma_tf32(float* d,
                                         uint32_t a0, uint32_t a1, uint32_t a2, uint32_t a3,
                                         uint32_t b0, uint32_t b1) {
    asm volatile(
        "mma.sync.aligned.m16n8k8.row.col.f32.tf32.tf32.f32 "
        "{%0,%1,%2,%3}, {%4,%5,%6,%7}, {%8,%9}, {%0,%1,%2,%3};"
        : "+f"(d[0]), "+f"(d[1]), "+f"(d[2]), "+f"(d[3])
        : "r"(a0), "r"(a1), "r"(a2), "r"(a3), "r"(b0), "r"(b1));
}

// ---------------------------------------------------------------------------
// Projection GEMM (tf32 mma) — unchanged (proven, ~720us)
// ---------------------------------------------------------------------------
#define XS_PITCH 20
#define WS_PITCH 136

__global__ __launch_bounds__(256, 2)
void proj_kernel(const float* __restrict__ X,
                 const float* __restrict__ Wq, const float* __restrict__ bq,
                 const float* __restrict__ Wk, const float* __restrict__ bk,
                 const float* __restrict__ Wv, const float* __restrict__ bv)
{
    const int z = blockIdx.z;
    const float* W    = (z == 0) ? Wq : (z == 1) ? Wk : Wv;
    const float* bias = (z == 0) ? bq : (z == 1) ? bk : bv;
    float* out = g_qkv + (size_t)z * TOK * D_DIM;

    const int m0 = blockIdx.y * 128;
    const int n0 = blockIdx.x * 128;

    __shared__ float Xs[2][128 * XS_PITCH];
    __shared__ float Ws[2][16 * WS_PITCH];

    const int t = threadIdx.x, w = t >> 5, lane = t & 31;
    const int wm = w >> 1, wn = w & 1;
    const int l4 = lane >> 2, lm = lane & 3;

    float acc[16][4];
#pragma unroll
    for (int i = 0; i < 16; ++i)
#pragma unroll
        for (int j = 0; j < 4; ++j) acc[i][j] = 0.f;

    float4 xa[2], wa[2];
#pragma unroll
    for (int i = 0; i < 2; ++i) {
        const int idx = t + i * 256;
        const int xr = idx >> 2, xq = idx & 3;
        xa[i] = *(const float4*)(X + (size_t)(m0 + xr) * D_DIM + xq * 4);
        const int wk = idx >> 5, nq = idx & 31;
        wa[i] = *(const float4*)(W + (size_t)wk * D_DIM + n0 + nq * 4);
    }
#pragma unroll
    for (int i = 0; i < 2; ++i) {
        const int idx = t + i * 256;
        const int xr = idx >> 2, xq = idx & 3;
        float* d = &Xs[0][xr * XS_PITCH + xq * 4];
        d[0] = rna_tf32(xa[i].x); d[1] = rna_tf32(xa[i].y);
        d[2] = rna_tf32(xa[i].z); d[3] = rna_tf32(xa[i].w);
        const int wk = idx >> 5, nq = idx & 31;
        float* d2 = &Ws[0][wk * WS_PITCH + nq * 4];
        d2[0] = rna_tf32(wa[i].x); d2[1] = rna_tf32(wa[i].y);
        d2[2] = rna_tf32(wa[i].z); d2[3] = rna_tf32(wa[i].w);
    }
    __syncthreads();

    for (int kt = 0; kt < 64; ++kt) {
        const int bf = kt & 1;
        if (kt < 63) {
#pragma unroll
            for (int i = 0; i < 2; ++i) {
                const int idx = t + i * 256;
                const int xr = idx >> 2, xq = idx & 3;
                xa[i] = *(const float4*)(X + (size_t)(m0 + xr) * D_DIM + (kt + 1) * 16 + xq * 4);
                const int wk = idx >> 5, nq = idx & 31;
                wa[i] = *(const float4*)(W + (size_t)((kt + 1) * 16 + wk) * D_DIM + n0 + nq * 4);
            }
        }
#pragma unroll
        for (int ks = 0; ks < 2; ++ks) {
            uint32_t a[2][4];
#pragma unroll
            for (int mt = 0; mt < 2; ++mt) {
                const float* Ar = &Xs[bf][(wm * 32 + mt * 16 + l4) * XS_PITCH + ks * 8 + lm];
                a[mt][0] = __float_as_uint(Ar[0]);
                a[mt][1] = __float_as_uint(Ar[8 * XS_PITCH]);
                a[mt][2] = __float_as_uint(Ar[4]);
                a[mt][3] = __float_as_uint(Ar[8 * XS_PITCH + 4]);
            }
            const float* Br = &Ws[bf][(ks * 8 + lm) * WS_PITCH + wn * 64 + l4];
#pragma unroll
            for (int nt = 0; nt < 8; ++nt) {
                const uint32_t b0 = __float_as_uint(Br[nt * 8]);
                const uint32_t b1 = __float_as_uint(Br[nt * 8 + 4 * WS_PITCH]);
                mma_tf32(acc[nt],     a[0][0], a[0][1], a[0][2], a[0][3], b0, b1);
                mma_tf32(acc[8 + nt], a[1][0], a[1][1], a[1][2], a[1][3], b0, b1);
            }
        }
        if (kt < 63) {
            const int nb = bf ^ 1;
#pragma unroll
            for (int i = 0; i < 2; ++i) {
                const int idx = t + i * 256;
                const int xr = idx >> 2, xq = idx & 3;
                float* d = &Xs[nb][xr * XS_PITCH + xq * 4];
                d[0] = rna_tf32(xa[i].x); d[1] = rna_tf32(xa[i].y);
                d[2] = rna_tf32(xa[i].z); d[3] = rna_tf32(xa[i].w);
                const int wk = idx >> 5, nq = idx & 31;
                float* d2 = &Ws[nb][wk * WS_PITCH + nq * 4];
                d2[0] = rna_tf32(wa[i].x); d2[1] = rna_tf32(wa[i].y);
                d2[2] = rna_tf32(wa[i].z); d2[3] = rna_tf32(wa[i].w);
            }
            __syncthreads();
        }
    }

#pragma unroll
    for (int mt = 0; mt < 2; ++mt) {
        const int r0 = m0 + wm * 32 + mt * 16 + l4;
#pragma unroll
        for (int nt = 0; nt < 8; ++nt) {
            const int cc = n0 + wn * 64 + nt * 8 + 2 * lm;
            const float bx = bias[cc], by = bias[cc + 1];
            float* a = acc[mt * 8 + nt];
            *(float2*)&out[(size_t)r0 * D_DIM + cc] =
                make_float2(rna_tf32(a[0] + bx), rna_tf32(a[1] + by));
            *(float2*)&out[(size_t)(r0 + 8) * D_DIM + cc] =
                make_float2(rna_tf32(a[2] + bx), rna_tf32(a[3] + by));
        }
    }
}

// ---------------------------------------------------------------------------
// Flash attention v5 = R2 kernel VERBATIM (256 thr, dual-barrier wait_group-1
// pipeline, prefetch depth 2) with exactly two compute-local deltas:
//  (1) no-rescale softmax (scores bounded => exp fp32-safe; shift-invariant)
//  (2) key-permuted P/V mma mapping -> V smem loads bank-conflict-free
// ---------------------------------------------------------------------------
#define QSP 1028
#define KVP 140
#define PSP 68
#define KVBUF (64 * KVP)
#define ATTN_SM_FLOATS (32 * QSP + 2 * KVBUF + 32 * PSP + 128 + 32)

__global__ __launch_bounds__(256, 1)
void attn_kernel(float* __restrict__ out)
{
    extern __shared__ float sm[];
    float* Qs   = sm;                      // [32][1028]
    float* KVs  = Qs + 32 * QSP;           // [2][64][140]
    float* Ps   = KVs + 2 * KVBUF;         // [32][68], key-permuted columns
    float* redl = Ps + 32 * PSP;           // [32][4]
    float* l_s  = redl + 128;              // [32]

    const int t = threadIdx.x, w = t >> 5, lane = t & 31;
    const int wm = w >> 2, wn = w & 3;
    const int l4 = lane >> 2, lm = lane & 3;
    const int b = blockIdx.y;
    const int qtile = (int)gridDim.x - 1 - (int)blockIdx.x;  // heavy tiles first
    const int qbase = qtile * 32;

    const float* qg = g_qkv + (size_t)b * S_LEN * D_DIM + (size_t)qbase * D_DIM;
    const float* kg = g_qkv + (size_t)TOK * D_DIM     + (size_t)b * S_LEN * D_DIM;
    const float* vg = g_qkv + (size_t)2 * TOK * D_DIM + (size_t)b * S_LEN * D_DIM;

    const uint32_t kv_smem = (uint32_t)__cvta_generic_to_shared(KVs);

    auto issue = [&](const float* base, int j0, int dc, int bfi) {
        const uint32_t dst = kv_smem + (uint32_t)bfi * (KVBUF * 4);
        const float* src0 = base + (size_t)j0 * D_DIM + dc * 128;
#pragma unroll
        for (int i = 0; i < 8; ++i) {
            const int idx = t + i * 256;
            const int row = idx >> 5, q4 = idx & 31;
            asm volatile("cp.async.cg.shared.global [%0], [%1], 16;"
                         :: "r"(dst + (uint32_t)(row * KVP + q4 * 4) * 4),
                            "l"(src0 + (size_t)row * D_DIM + q4 * 4)
                         : "memory");
        }
        asm volatile("cp.async.commit_group;" ::: "memory");
    };

    issue(kg, 0, 0, 0);   // prefetch K chunk0 stage0 while staging Q

    // stage Q tile (already tf32-rounded by proj)
#pragma unroll
    for (int i = 0; i < 32; ++i) {
        const int idx = t + i * 256;       // 8192 float4
        const int row = idx >> 8, c4 = idx & 255;
        *(float4*)&Qs[row * QSP + c4 * 4] =
            *(const float4*)(qg + (size_t)row * D_DIM + c4 * 4);
    }

    float oacc[128];
#pragma unroll
    for (int i = 0; i < 128; ++i) oacc[i] = 0.f;
    float lsum0 = 0.f, lsum1 = 0.f;

    const int kcmax = (qbase + 31) >> 6;
    int bf = 0;

    for (int kc = 0; kc <= kcmax; ++kc) {
        const int j0 = kc << 6;
        float sacc[2][4] = {{0.f, 0.f, 0.f, 0.f}, {0.f, 0.f, 0.f, 0.f}};

        // ---- S = Q K^T, 8 stages of d=128 (R2 pipeline: depth-2 prefetch) ----
        for (int dc = 0; dc < 8; ++dc) {
            __syncthreads();
            if (dc < 7) issue(kg, j0, dc + 1, bf ^ 1);
            else        issue(vg, j0, 0,      bf ^ 1);
            asm volatile("cp.async.wait_group 1;" ::: "memory");
            __syncthreads();
            const float* KB  = KVs + bf * KVBUF;
            const float* Qr0 = Qs + (wm * 16 + l4) * QSP + dc * 128;
            const float* Qr1 = Qr0 + 8 * QSP;
            const float* K0  = KB + (wn * 16 + l4) * KVP;
            const float* K1  = K0 + 8 * KVP;
#pragma unroll 4
            for (int ks = 0; ks < 16; ++ks) {
                const int c0 = ks * 8 + lm;
                const uint32_t a0 = __float_as_uint(Qr0[c0]);
                const uint32_t a1 = __float_as_uint(Qr1[c0]);
                const uint32_t a2 = __float_as_uint(Qr0[c0 + 4]);
                const uint32_t a3 = __float_as_uint(Qr1[c0 + 4]);
                const uint32_t b00 = __float_as_uint(K0[c0]);
                const uint32_t b01 = __float_as_uint(K0[c0 + 4]);
                const uint32_t b10 = __float_as_uint(K1[c0]);
                const uint32_t b11 = __float_as_uint(K1[c0 + 4]);
                mma_tf32(sacc[0], a0, a1, a2, a3, b00, b01);
                mma_tf32(sacc[1], a0, a1, a2, a3, b10, b11);
            }
            bf ^= 1;
        }

        // ---- softmax, no max-shift: p = exp(s/32); key-permuted P store ----
        // key (g*8 + 2j)   -> P col g*8 + j       (j = lm)
        // key (g*8 + 2j+1) -> P col g*8 + 4 + j
        {
            const int row0 = qbase + wm * 16 + l4;
            float* Pr0 = Ps + (wm * 16 + l4) * PSP;
            float* Pr1 = Pr0 + 8 * PSP;
#pragma unroll
            for (int t8 = 0; t8 < 2; ++t8) {
                const int cb = j0 + wn * 16 + t8 * 8 + 2 * lm;
                const float p0 = (cb     <= row0)     ? __expf(sacc[t8][0] * 0.03125f) : 0.f;
                const float p1 = (cb + 1 <= row0)     ? __expf(sacc[t8][1] * 0.03125f) : 0.f;
                const float p2 = (cb     <= row0 + 8) ? __expf(sacc[t8][2] * 0.03125f) : 0.f;
                const float p3 = (cb + 1 <= row0 + 8) ? __expf(sacc[t8][3] * 0.03125f) : 0.f;
                lsum0 += p0 + p1;
                lsum1 += p2 + p3;
                const int cp = (wn * 2 + t8) * 8 + lm;
                Pr0[cp]     = rna_tf32(p0);
                Pr0[cp + 4] = rna_tf32(p1);
                Pr1[cp]     = rna_tf32(p2);
                Pr1[cp + 4] = rna_tf32(p3);
            }
        }
        // Ps published by the first barrier of the PV loop below.

        // ---- O += P @ V, 8 stages of d=128 (R2 pipeline), permuted k-map ----
#pragma unroll 1
        for (int dc = 0; dc < 8; ++dc) {
            __syncthreads();
            if (dc < 7) {
                issue(vg, j0, dc + 1, bf ^ 1);
                asm volatile("cp.async.wait_group 1;" ::: "memory");
            } else if (kc < kcmax) {
                issue(kg, j0 + 64, 0, bf ^ 1);
                asm volatile("cp.async.wait_group 1;" ::: "memory");
            } else {
                asm volatile("cp.async.wait_group 0;" ::: "memory");
            }
            __syncthreads();
            const float* VB  = KVs + bf * KVBUF;
            const float* Pr0 = Ps + (wm * 16 + l4) * PSP;
            const float* Pr1 = Pr0 + 8 * PSP;
#pragma unroll 2
            for (int ks = 0; ks < 8; ++ks) {
                const int cp = ks * 8 + lm;
                const uint32_t a0 = __float_as_uint(Pr0[cp]);       // key ks*8+2lm
                const uint32_t a1 = __float_as_uint(Pr1[cp]);
                const uint32_t a2 = __float_as_uint(Pr0[cp + 4]);   // key ks*8+2lm+1
                const uint32_t a3 = __float_as_uint(Pr1[cp + 4]);
                const float* Ve = VB + (ks * 8 + 2 * lm) * KVP + wn * 32 + l4;  // even key
                const float* Vo = Ve + KVP;                                     // odd key
#pragma unroll
                for (int nt = 0; nt < 4; ++nt) {
                    const uint32_t b0 = __float_as_uint(Ve[nt * 8]);
                    const uint32_t b1 = __float_as_uint(Vo[nt * 8]);
                    mma_tf32(&oacc[dc * 16 + nt * 4], a0, a1, a2, a3, b0, b1);
                }
            }
            bf ^= 1;
        }
    }

    // ---- final l reduction (once per kernel) ----
    lsum0 += __shfl_xor_sync(0xffffffffu, lsum0, 1);
    lsum0 += __shfl_xor_sync(0xffffffffu, lsum0, 2);
    lsum1 += __shfl_xor_sync(0xffffffffu, lsum1, 1);
    lsum1 += __shfl_xor_sync(0xffffffffu, lsum1, 2);
    if (lm == 0) {
        redl[(wm * 16 + l4) * 4 + wn]     = lsum0;
        redl[(wm * 16 + l4 + 8) * 4 + wn] = lsum1;
    }
    __syncthreads();
    if (t < 32)
        l_s[t] = redl[t * 4] + redl[t * 4 + 1] + redl[t * 4 + 2] + redl[t * 4 + 3];
    __syncthreads();

    const float inv0 = 1.0f / l_s[wm * 16 + l4];
    const float inv1 = 1.0f / l_s[wm * 16 + l4 + 8];
    float* og0 = out + (size_t)b * S_LEN * D_DIM + (size_t)(qbase + wm * 16 + l4) * D_DIM;
    float* og1 = og0 + 8 * D_DIM;
#pragma unroll
    for (int dc = 0; dc < 8; ++dc)
#pragma unroll
        for (int nt = 0; nt < 4; ++nt) {
            const int cc = dc * 128 + wn * 32 + nt * 8 + 2 * lm;
            const float* oa = &oacc[dc * 16 + nt * 4];
            *(float2*)&og0[cc] = make_float2(oa[0] * inv0, oa[1] * inv0);
            *(float2*)&og1[cc] = make_float2(oa[2] * inv1, oa[3] * inv1);
        }
}

// ---------------------------------------------------------------------------
extern "C" void kernel_launch(void* const* d_in, const int* in_sizes, int n_in,
                              void* d_out, int out_size)
{
    const float* x  = (const float*)d_in[0];
    const float* Wq = (const float*)d_in[1];
    const float* bq = (const float*)d_in[2];
    const float* Wk = (const float*)d_in[3];
    const float* bk = (const float*)d_in[4];
    const float* Wv = (const float*)d_in[5];
    const float* bv = (const float*)d_in[6];
    float* out = (float*)d_out;

    dim3 pg(D_DIM / 128, TOK / 128, 3);
    proj_kernel<<<pg, 256>>>(x, Wq, bq, Wk, bk, Wv, bv);

    const size_t attn_smem = (size_t)ATTN_SM_FLOATS * sizeof(float);   // ~212.6 KB
    cudaFuncSetAttribute(attn_kernel, cudaFuncAttributeMaxDynamicSharedMemorySize,
                         (int)attn_smem);
    dim3 ag(S_LEN / 32, BATCH);
    attn_kernel<<<ag, 256, attn_smem>>>(out);
}

// round 14
// speedup vs baseline: 1.4940x; 1.4747x over previous
#include <cuda_runtime.h>
#include <cstdint>

#define S_LEN 4096
#define D_DIM 1024
#define BATCH 4
#define TOK   (BATCH * S_LEN)   // 16384

__device__ float g_qkv[(size_t)3 * TOK * D_DIM];

__device__ __forceinline__ float rna_tf32(float x) {
    uint32_t u;
    asm("cvt.rna.tf32.f32 %0, %1;" : "=r"(u) : "f"(x));
    return __uint_as_float(u);
}

__device__ __forceinline__ void mma_tf32(float* d,
                                         uint32_t a0, uint32_t a1, uint32_t a2, uint32_t a3,
                                         uint32_t b0, uint32_t b1) {
    asm volatile(
        "mma.sync.aligned.m16n8k8.row.col.f32.tf32.tf32.f32 "
        "{%0,%1,%2,%3}, {%4,%5,%6,%7}, {%8,%9}, {%0,%1,%2,%3};"
        : "+f"(d[0]), "+f"(d[1]), "+f"(d[2]), "+f"(d[3])
        : "r"(a0), "r"(a1), "r"(a2), "r"(a3), "r"(b0), "r"(b1));
}

// ---------------------------------------------------------------------------
// Projection GEMM (tf32 mma) — unchanged (proven, ~720us)
// ---------------------------------------------------------------------------
#define XS_PITCH 20
#define WS_PITCH 136

__global__ __launch_bounds__(256, 2)
void proj_kernel(const float* __restrict__ X,
                 const float* __restrict__ Wq, const float* __restrict__ bq,
                 const float* __restrict__ Wk, const float* __restrict__ bk,
                 const float* __restrict__ Wv, const float* __restrict__ bv)
{
    const int z = blockIdx.z;
    const float* W    = (z == 0) ? Wq : (z == 1) ? Wk : Wv;
    const float* bias = (z == 0) ? bq : (z == 1) ? bk : bv;
    float* out = g_qkv + (size_t)z * TOK * D_DIM;

    const int m0 = blockIdx.y * 128;
    const int n0 = blockIdx.x * 128;

    __shared__ float Xs[2][128 * XS_PITCH];
    __shared__ float Ws[2][16 * WS_PITCH];

    const int t = threadIdx.x, w = t >> 5, lane = t & 31;
    const int wm = w >> 1, wn = w & 1;
    const int l4 = lane >> 2, lm = lane & 3;

    float acc[16][4];
#pragma unroll
    for (int i = 0; i < 16; ++i)
#pragma unroll
        for (int j = 0; j < 4; ++j) acc[i][j] = 0.f;

    float4 xa[2], wa[2];
#pragma unroll
    for (int i = 0; i < 2; ++i) {
        const int idx = t + i * 256;
        const int xr = idx >> 2, xq = idx & 3;
        xa[i] = *(const float4*)(X + (size_t)(m0 + xr) * D_DIM + xq * 4);
        const int wk = idx >> 5, nq = idx & 31;
        wa[i] = *(const float4*)(W + (size_t)wk * D_DIM + n0 + nq * 4);
    }
#pragma unroll
    for (int i = 0; i < 2; ++i) {
        const int idx = t + i * 256;
        const int xr = idx >> 2, xq = idx & 3;
        float* d = &Xs[0][xr * XS_PITCH + xq * 4];
        d[0] = rna_tf32(xa[i].x); d[1] = rna_tf32(xa[i].y);
        d[2] = rna_tf32(xa[i].z); d[3] = rna_tf32(xa[i].w);
        const int wk = idx >> 5, nq = idx & 31;
        float* d2 = &Ws[0][wk * WS_PITCH + nq * 4];
        d2[0] = rna_tf32(wa[i].x); d2[1] = rna_tf32(wa[i].y);
        d2[2] = rna_tf32(wa[i].z); d2[3] = rna_tf32(wa[i].w);
    }
    __syncthreads();

    for (int kt = 0; kt < 64; ++kt) {
        const int bf = kt & 1;
        if (kt < 63) {
#pragma unroll
            for (int i = 0; i < 2; ++i) {
                const int idx = t + i * 256;
                const int xr = idx >> 2, xq = idx & 3;
                xa[i] = *(const float4*)(X + (size_t)(m0 + xr) * D_DIM + (kt + 1) * 16 + xq * 4);
                const int wk = idx >> 5, nq = idx & 31;
                wa[i] = *(const float4*)(W + (size_t)((kt + 1) * 16 + wk) * D_DIM + n0 + nq * 4);
            }
        }
#pragma unroll
        for (int ks = 0; ks < 2; ++ks) {
            uint32_t a[2][4];
#pragma unroll
            for (int mt = 0; mt < 2; ++mt) {
                const float* Ar = &Xs[bf][(wm * 32 + mt * 16 + l4) * XS_PITCH + ks * 8 + lm];
                a[mt][0] = __float_as_uint(Ar[0]);
                a[mt][1] = __float_as_uint(Ar[8 * XS_PITCH]);
                a[mt][2] = __float_as_uint(Ar[4]);
                a[mt][3] = __float_as_uint(Ar[8 * XS_PITCH + 4]);
            }
            const float* Br = &Ws[bf][(ks * 8 + lm) * WS_PITCH + wn * 64 + l4];
#pragma unroll
            for (int nt = 0; nt < 8; ++nt) {
                const uint32_t b0 = __float_as_uint(Br[nt * 8]);
                const uint32_t b1 = __float_as_uint(Br[nt * 8 + 4 * WS_PITCH]);
                mma_tf32(acc[nt],     a[0][0], a[0][1], a[0][2], a[0][3], b0, b1);
                mma_tf32(acc[8 + nt], a[1][0], a[1][1], a[1][2], a[1][3], b0, b1);
            }
        }
        if (kt < 63) {
            const int nb = bf ^ 1;
#pragma unroll
            for (int i = 0; i < 2; ++i) {
                const int idx = t + i * 256;
                const int xr = idx >> 2, xq = idx & 3;
                float* d = &Xs[nb][xr * XS_PITCH + xq * 4];
                d[0] = rna_tf32(xa[i].x); d[1] = rna_tf32(xa[i].y);
                d[2] = rna_tf32(xa[i].z); d[3] = rna_tf32(xa[i].w);
                const int wk = idx >> 5, nq = idx & 31;
                float* d2 = &Ws[nb][wk * WS_PITCH + nq * 4];
                d2[0] = rna_tf32(wa[i].x); d2[1] = rna_tf32(wa[i].y);
                d2[2] = rna_tf32(wa[i].z); d2[3] = rna_tf32(wa[i].w);
            }
            __syncthreads();
        }
    }

#pragma unroll
    for (int mt = 0; mt < 2; ++mt) {
        const int r0 = m0 + wm * 32 + mt * 16 + l4;
#pragma unroll
        for (int nt = 0; nt < 8; ++nt) {
            const int cc = n0 + wn * 64 + nt * 8 + 2 * lm;
            const float bx = bias[cc], by = bias[cc + 1];
            float* a = acc[mt * 8 + nt];
            *(float2*)&out[(size_t)r0 * D_DIM + cc] =
                make_float2(rna_tf32(a[0] + bx), rna_tf32(a[1] + by));
            *(float2*)&out[(size_t)(r0 + 8) * D_DIM + cc] =
                make_float2(rna_tf32(a[2] + bx), rna_tf32(a[3] + by));
        }
    }
}

// ---------------------------------------------------------------------------
// Flash attention v6 = R13 with ONE change: the PV dc loop is fully unrolled
// so oacc[] indices are compile-time constants and O stays register-resident
// (R13's `#pragma unroll 1` forced dynamic indexing -> local-memory spill of
// the whole 128-float accumulator; regs 236->160, the entire R5..R13 regression).
// Deltas vs R2 retained: no-rescale softmax, key-permuted conflict-free P/V map.
// ---------------------------------------------------------------------------
#define QSP 1028
#define KVP 140
#define PSP 68
#define KVBUF (64 * KVP)
#define ATTN_SM_FLOATS (32 * QSP + 2 * KVBUF + 32 * PSP + 128 + 32)

__global__ __launch_bounds__(256, 1)
void attn_kernel(float* __restrict__ out)
{
    extern __shared__ float sm[];
    float* Qs   = sm;                      // [32][1028]
    float* KVs  = Qs + 32 * QSP;           // [2][64][140]
    float* Ps   = KVs + 2 * KVBUF;         // [32][68], key-permuted columns
    float* redl = Ps + 32 * PSP;           // [32][4]
    float* l_s  = redl + 128;              // [32]

    const int t = threadIdx.x, w = t >> 5, lane = t & 31;
    const int wm = w >> 2, wn = w & 3;
    const int l4 = lane >> 2, lm = lane & 3;
    const int b = blockIdx.y;
    const int qtile = (int)gridDim.x - 1 - (int)blockIdx.x;  // heavy tiles first
    const int qbase = qtile * 32;

    const float* qg = g_qkv + (size_t)b * S_LEN * D_DIM + (size_t)qbase * D_DIM;
    const float* kg = g_qkv + (size_t)TOK * D_DIM     + (size_t)b * S_LEN * D_DIM;
    const float* vg = g_qkv + (size_t)2 * TOK * D_DIM + (size_t)b * S_LEN * D_DIM;

    const uint32_t kv_smem = (uint32_t)__cvta_generic_to_shared(KVs);

    auto issue = [&](const float* base, int j0, int dc, int bfi) {
        const uint32_t dst = kv_smem + (uint32_t)bfi * (KVBUF * 4);
        const float* src0 = base + (size_t)j0 * D_DIM + dc * 128;
#pragma unroll
        for (int i = 0; i < 8; ++i) {
            const int idx = t + i * 256;
            const int row = idx >> 5, q4 = idx & 31;
            asm volatile("cp.async.cg.shared.global [%0], [%1], 16;"
                         :: "r"(dst + (uint32_t)(row * KVP + q4 * 4) * 4),
                            "l"(src0 + (size_t)row * D_DIM + q4 * 4)
                         : "memory");
        }
        asm volatile("cp.async.commit_group;" ::: "memory");
    };

    issue(kg, 0, 0, 0);   // prefetch K chunk0 stage0 while staging Q

    // stage Q tile (already tf32-rounded by proj)
#pragma unroll
    for (int i = 0; i < 32; ++i) {
        const int idx = t + i * 256;       // 8192 float4
        const int row = idx >> 8, c4 = idx & 255;
        *(float4*)&Qs[row * QSP + c4 * 4] =
            *(const float4*)(qg + (size_t)row * D_DIM + c4 * 4);
    }

    float oacc[128];
#pragma unroll
    for (int i = 0; i < 128; ++i) oacc[i] = 0.f;
    float lsum0 = 0.f, lsum1 = 0.f;

    const int kcmax = (qbase + 31) >> 6;
    int bf = 0;

    for (int kc = 0; kc <= kcmax; ++kc) {
        const int j0 = kc << 6;
        float sacc[2][4] = {{0.f, 0.f, 0.f, 0.f}, {0.f, 0.f, 0.f, 0.f}};

        // ---- S = Q K^T, 8 stages of d=128 (depth-2 prefetch pipeline) ----
        for (int dc = 0; dc < 8; ++dc) {
            __syncthreads();
            if (dc < 7) issue(kg, j0, dc + 1, bf ^ 1);
            else        issue(vg, j0, 0,      bf ^ 1);
            asm volatile("cp.async.wait_group 1;" ::: "memory");
            __syncthreads();
            const float* KB  = KVs + bf * KVBUF;
            const float* Qr0 = Qs + (wm * 16 + l4) * QSP + dc * 128;
            const float* Qr1 = Qr0 + 8 * QSP;
            const float* K0  = KB + (wn * 16 + l4) * KVP;
            const float* K1  = K0 + 8 * KVP;
#pragma unroll 4
            for (int ks = 0; ks < 16; ++ks) {
                const int c0 = ks * 8 + lm;
                const uint32_t a0 = __float_as_uint(Qr0[c0]);
                const uint32_t a1 = __float_as_uint(Qr1[c0]);
                const uint32_t a2 = __float_as_uint(Qr0[c0 + 4]);
                const uint32_t a3 = __float_as_uint(Qr1[c0 + 4]);
                const uint32_t b00 = __float_as_uint(K0[c0]);
                const uint32_t b01 = __float_as_uint(K0[c0 + 4]);
                const uint32_t b10 = __float_as_uint(K1[c0]);
                const uint32_t b11 = __float_as_uint(K1[c0 + 4]);
                mma_tf32(sacc[0], a0, a1, a2, a3, b00, b01);
                mma_tf32(sacc[1], a0, a1, a2, a3, b10, b11);
            }
            bf ^= 1;
        }

        // ---- softmax, no max-shift: p = exp(s/32); key-permuted P store ----
        // key (g*8 + 2j)   -> P col g*8 + j       (j = lm)
        // key (g*8 + 2j+1) -> P col g*8 + 4 + j
        {
            const int row0 = qbase + wm * 16 + l4;
            float* Pr0 = Ps + (wm * 16 + l4) * PSP;
            float* Pr1 = Pr0 + 8 * PSP;
#pragma unroll
            for (int t8 = 0; t8 < 2; ++t8) {
                const int cb = j0 + wn * 16 + t8 * 8 + 2 * lm;
                const float p0 = (cb     <= row0)     ? __expf(sacc[t8][0] * 0.03125f) : 0.f;
                const float p1 = (cb + 1 <= row0)     ? __expf(sacc[t8][1] * 0.03125f) : 0.f;
                const float p2 = (cb     <= row0 + 8) ? __expf(sacc[t8][2] * 0.03125f) : 0.f;
                const float p3 = (cb + 1 <= row0 + 8) ? __expf(sacc[t8][3] * 0.03125f) : 0.f;
                lsum0 += p0 + p1;
                lsum1 += p2 + p3;
                const int cp = (wn * 2 + t8) * 8 + lm;
                Pr0[cp]     = rna_tf32(p0);
                Pr0[cp + 4] = rna_tf32(p1);
                Pr1[cp]     = rna_tf32(p2);
                Pr1[cp + 4] = rna_tf32(p3);
            }
        }
        // Ps published by the first barrier of the PV loop below.

        // ---- O += P @ V, 8 stages of d=128, FULLY UNROLLED (O in registers) ----
#pragma unroll
        for (int dc = 0; dc < 8; ++dc) {
            __syncthreads();
            if (dc < 7) {
                issue(vg, j0, dc + 1, bf ^ 1);
                asm volatile("cp.async.wait_group 1;" ::: "memory");
            } else if (kc < kcmax) {
                issue(kg, j0 + 64, 0, bf ^ 1);
                asm volatile("cp.async.wait_group 1;" ::: "memory");
            } else {
                asm volatile("cp.async.wait_group 0;" ::: "memory");
            }
            __syncthreads();
            const float* VB  = KVs + bf * KVBUF;
            const float* Pr0 = Ps + (wm * 16 + l4) * PSP;
            const float* Pr1 = Pr0 + 8 * PSP;
#pragma unroll 2
            for (int ks = 0; ks < 8; ++ks) {
                const int cp = ks * 8 + lm;
                const uint32_t a0 = __float_as_uint(Pr0[cp]);       // key ks*8+2lm
                const uint32_t a1 = __float_as_uint(Pr1[cp]);
                const uint32_t a2 = __float_as_uint(Pr0[cp + 4]);   // key ks*8+2lm+1
                const uint32_t a3 = __float_as_uint(Pr1[cp + 4]);
                const float* Ve = VB + (ks * 8 + 2 * lm) * KVP + wn * 32 + l4;  // even key
                const float* Vo = Ve + KVP;                                     // odd key
#pragma unroll
                for (int nt = 0; nt < 4; ++nt) {
                    const uint32_t b0 = __float_as_uint(Ve[nt * 8]);
                    const uint32_t b1 = __float_as_uint(Vo[nt * 8]);
                    mma_tf32(&oacc[dc * 16 + nt * 4], a0, a1, a2, a3, b0, b1);
                }
            }
            bf ^= 1;
        }
    }

    // ---- final l reduction (once per kernel) ----
    lsum0 += __shfl_xor_sync(0xffffffffu, lsum0, 1);
    lsum0 += __shfl_xor_sync(0xffffffffu, lsum0, 2);
    lsum1 += __shfl_xor_sync(0xffffffffu, lsum1, 1);
    lsum1 += __shfl_xor_sync(0xffffffffu, lsum1, 2);
    if (lm == 0) {
        redl[(wm * 16 + l4) * 4 + wn]     = lsum0;
        redl[(wm * 16 + l4 + 8) * 4 + wn] = lsum1;
    }
    __syncthreads();
    if (t < 32)
        l_s[t] = redl[t * 4] + redl[t * 4 + 1] + redl[t * 4 + 2] + redl[t * 4 + 3];
    __syncthreads();

    const float inv0 = 1.0f / l_s[wm * 16 + l4];
    const float inv1 = 1.0f / l_s[wm * 16 + l4 + 8];
    float* og0 = out + (size_t)b * S_LEN * D_DIM + (size_t)(qbase + wm * 16 + l4) * D_DIM;
    float* og1 = og0 + 8 * D_DIM;
#pragma unroll
    for (int dc = 0; dc < 8; ++dc)
#pragma unroll
        for (int nt = 0; nt < 4; ++nt) {
            const int cc = dc * 128 + wn * 32 + nt * 8 + 2 * lm;
            const float* oa = &oacc[dc * 16 + nt * 4];
            *(float2*)&og0[cc] = make_float2(oa[0] * inv0, oa[1] * inv0);
            *(float2*)&og1[cc] = make_float2(oa[2] * inv1, oa[3] * inv1);
        }
}

// ---------------------------------------------------------------------------
extern "C" void kernel_launch(void* const* d_in, const int* in_sizes, int n_in,
                              void* d_out, int out_size)
{
    const float* x  = (const float*)d_in[0];
    const float* Wq = (const float*)d_in[1];
    const float* bq = (const float*)d_in[2];
    const float* Wk = (const float*)d_in[3];
    const float* bk = (const float*)d_in[4];
    const float* Wv = (const float*)d_in[5];
    const float* bv = (const float*)d_in[6];
    float* out = (float*)d_out;

    dim3 pg(D_DIM / 128, TOK / 128, 3);
    proj_kernel<<<pg, 256>>>(x, Wq, bq, Wk, bk, Wv, bv);

    const size_t attn_smem = (size_t)ATTN_SM_FLOATS * sizeof(float);   // ~212.6 KB
    cudaFuncSetAttribute(attn_kernel, cudaFuncAttributeMaxDynamicSharedMemorySize,
                         (int)attn_smem);
    dim3 ag(S_LEN / 32, BATCH);
    attn_kernel<<<ag, 256, attn_smem>>>(out);
}